// round 17
// baseline (speedup 1.0000x reference)
#include <cuda_runtime.h>
#include <cuda_fp16.h>
#include <cstdint>

#define N_NODES 100000
#define N_EDGES 1600000
#define N_GRAPHS 64
#define EMBED 64
#define HIDDEN 128
#define GEMM_GRID 296   // 2 blocks/SM on 148 SMs -> single wave
#define CSR_BLOCKS ((N_EDGES + 511) / 512)   // 3125

// ---------------- scratch (static device globals; no allocation) ----------------
// Referenced ONLY from device code (host-side use of __device__ symbols binds
// the shadow symbol -> the R9 guard violation).
__device__ __half g_h0h[N_NODES * EMBED];       // embedded features fp16 12.8 MB
__device__ __half g_mh[N_NODES * HIDDEN];       // dinv * (h @ W), fp16   25.6 MB
__device__ __half g_xh[N_NODES * HIDDEN];       // relu'd activations     25.6 MB
__device__ int    g_csr32[N_EDGES];             // src only (coef folded)  6.4 MB
__device__ int    g_rowptr[N_NODES + 1];
__device__ int    g_cursor[N_NODES];
__device__ int    g_deg[N_NODES];
__device__ float  g_dinv[N_NODES];
__device__ int    g_part[512];
__device__ float  g_pool[N_GRAPHS * HIDDEN];
__device__ float  g_cnt[N_GRAPHS];
__device__ int    g_is64;

// ---------------- f32x2 helpers (edge accumulate) ----------------
__device__ __forceinline__ unsigned long long pack2(float x, float y) {
    unsigned long long r;
    asm("mov.b64 %0, {%1, %2};" : "=l"(r) : "f"(x), "f"(y));
    return r;
}
__device__ __forceinline__ float2 unpack2(unsigned long long v) {
    float2 r;
    asm("mov.b64 {%0, %1}, %2;" : "=f"(r.x), "=f"(r.y) : "l"(v));
    return r;
}
__device__ __forceinline__ void fma2(unsigned long long& d, unsigned long long a,
                                     unsigned long long b) {
    asm("fma.rn.f32x2 %0, %1, %2, %0;" : "+l"(d) : "l"(a), "l"(b));
}

// ---------------- cp.async helpers ----------------
__device__ __forceinline__ void cp16(uint32_t dst, const void* src, int srcsize) {
    asm volatile("cp.async.cg.shared.global [%0], [%1], 16, %2;"
                 :: "r"(dst), "l"(src), "r"(srcsize) : "memory");
}
#define CP_COMMIT() asm volatile("cp.async.commit_group;" ::: "memory")
#define CP_WAIT(n)  asm volatile("cp.async.wait_group %0;" :: "n"(n) : "memory")

// ---------------- mma / ldmatrix helpers ----------------
__device__ __forceinline__ void ldsm_x4(uint32_t& r0, uint32_t& r1, uint32_t& r2,
                                        uint32_t& r3, uint32_t addr) {
    asm volatile("ldmatrix.sync.aligned.m8n8.x4.shared.b16 {%0,%1,%2,%3}, [%4];"
                 : "=r"(r0), "=r"(r1), "=r"(r2), "=r"(r3) : "r"(addr));
}
__device__ __forceinline__ void ldsm_x4_t(uint32_t& r0, uint32_t& r1, uint32_t& r2,
                                          uint32_t& r3, uint32_t addr) {
    asm volatile("ldmatrix.sync.aligned.m8n8.x4.trans.shared.b16 {%0,%1,%2,%3}, [%4];"
                 : "=r"(r0), "=r"(r1), "=r"(r2), "=r"(r3) : "r"(addr));
}
__device__ __forceinline__ void mma16816(float* c, uint32_t a0, uint32_t a1,
                                         uint32_t a2, uint32_t a3,
                                         uint32_t b0, uint32_t b1) {
    asm volatile(
        "mma.sync.aligned.m16n8k16.row.col.f32.f16.f16.f32 "
        "{%0,%1,%2,%3}, {%4,%5,%6,%7}, {%8,%9}, {%0,%1,%2,%3};"
        : "+f"(c[0]), "+f"(c[1]), "+f"(c[2]), "+f"(c[3])
        : "r"(a0), "r"(a1), "r"(a2), "r"(a3), "r"(b0), "r"(b1));
}

__device__ __forceinline__ long long load_idx(const void* p, int i, int is64) {
    if (is64) return ((const long long*)p)[i];
    return (long long)((const int*)p)[i];
}

// ---------------- init: zero counters + parallel dtype detection ----------------
__global__ void k_init(const void* ei) {
    int i = blockIdx.x * blockDim.x + threadIdx.x;
    if (i < N_NODES) g_deg[i] = 0;
    if (i < N_GRAPHS * HIDDEN) g_pool[i] = 0.0f;
    if (i < N_GRAPHS) g_cnt[i] = 0.0f;
    if (blockIdx.x == 0) {
        __shared__ int s_ok;
        if (threadIdx.x == 0) s_ok = 1;
        __syncthreads();
        const unsigned long long* p = (const unsigned long long*)ei;
        int bad = 0;
        for (int t = threadIdx.x; t < 1000; t += 256)
            if (p[t] >= (unsigned long long)N_NODES) bad = 1;
        if (bad) atomicAnd(&s_ok, 0);
        __syncthreads();
        if (threadIdx.x == 0) g_is64 = s_ok;
    }
}

// ---------------- fused: degree count + embedding gather ----------------
__global__ void k_count_embed(const void* ei, const void* x,
                              const float* __restrict__ emb) {
    int is64 = g_is64;
    int t = blockIdx.x * blockDim.x + threadIdx.x;
    if (t < N_EDGES) {
        int d = (int)load_idx(ei, N_EDGES + t, is64);
        atomicAdd(&g_deg[d], 1);
    }
    if (t < N_NODES * (EMBED / 4)) {
        int node = t >> 4;
        int q = t & 15;
        long long xi = load_idx(x, node, is64);
        float4 v = reinterpret_cast<const float4*>(emb)[xi * (EMBED / 4) + q];
        __half2 h0 = __floats2half2_rn(v.x, v.y);
        __half2 h1 = __floats2half2_rn(v.z, v.w);
        uint2 u = make_uint2(*reinterpret_cast<uint32_t*>(&h0),
                             *reinterpret_cast<uint32_t*>(&h1));
        reinterpret_cast<uint2*>(g_h0h)[t] = u;
    }
}

// ---------------- prep scans ----------------
__global__ void __launch_bounds__(256) k_scan1() {
    __shared__ int s[256];
    int tid = threadIdx.x;
    int n = blockIdx.x * 256 + tid;
    int d = (n < N_NODES) ? g_deg[n] : 0;
    if (n < N_NODES) g_dinv[n] = rsqrtf((float)d + 1.0f);
    s[tid] = d;
    __syncthreads();
#pragma unroll
    for (int off = 1; off < 256; off <<= 1) {
        int v = (tid >= off) ? s[tid - off] : 0;
        __syncthreads();
        s[tid] += v;
        __syncthreads();
    }
    if (n < N_NODES) g_rowptr[n] = s[tid] - d;
    if (tid == 255) g_part[blockIdx.x] = s[255];
}

__global__ void __launch_bounds__(512) k_scan2() {
    __shared__ int s[512];
    int tid = threadIdx.x;
    int v0 = (tid < 391) ? g_part[tid] : 0;
    s[tid] = v0;
    __syncthreads();
#pragma unroll
    for (int off = 1; off < 512; off <<= 1) {
        int v = (tid >= off) ? s[tid - off] : 0;
        __syncthreads();
        s[tid] += v;
        __syncthreads();
    }
    if (tid < 391) g_part[tid] = s[tid] - v0;
}

__global__ void k_scan3() {
    int n = blockIdx.x * blockDim.x + threadIdx.x;
    if (n < N_NODES) {
        int v = g_rowptr[n] + g_part[n >> 8];
        g_rowptr[n] = v;
        g_cursor[n] = v;
    }
    if (n == 0) g_rowptr[N_NODES] = N_EDGES;
}

// ---------------- GEMM body (device fn; pipelined, persistent) ----------------
// g_mh = half(dinv[row] * (in @ W)); cp.async double-buffered A staging.
template <int IN, bool FROM_H0>
__device__ __forceinline__ void gemm_body(const float* __restrict__ W) {
    const __half* in = FROM_H0 ? g_h0h : g_xh;
    constexpr int SA = IN + 8;
    constexpr int SW = HIDDEN + 8;
    constexpr int NCHUNK = (N_NODES + 127) / 128;   // 782
    constexpr int PER_ROW = IN / 8;                 // 16B lines per A row
    constexpr int LINES = 128 * PER_ROW;
    extern __shared__ __half smem[];
    __half* sW = smem;                              // IN x SW
    __half* sA0 = smem + IN * SW;                   // 128 x SA
    __half* sA1 = sA0 + 128 * SA;                   // 128 x SA
    int tid = threadIdx.x;

    // stage W once (fp32 -> fp16)
    for (int t = tid; t < IN * HIDDEN / 4; t += 512) {
        int k = t / (HIDDEN / 4);
        int nc = t % (HIDDEN / 4);
        float4 v = *reinterpret_cast<const float4*>(&W[k * HIDDEN + nc * 4]);
        __half2 h0 = __floats2half2_rn(v.x, v.y);
        __half2 h1 = __floats2half2_rn(v.z, v.w);
        uint2 u = make_uint2(*reinterpret_cast<uint32_t*>(&h0),
                             *reinterpret_cast<uint32_t*>(&h1));
        *reinterpret_cast<uint2*>(&sW[k * SW + nc * 4]) = u;
    }

    uint32_t sA0u = (uint32_t)__cvta_generic_to_shared(sA0);
    uint32_t sA1u = (uint32_t)__cvta_generic_to_shared(sA1);

    int lane = tid & 31;
    int wid = tid >> 5;
    int mg = wid >> 1;
    int wh = wid & 1;
    int lrow = lane & 15;
    int lcol = lane >> 4;
    uint32_t aOff = ((mg * 16 + lrow) * SA + lcol * 8) * 2;
    uint32_t wBase = (uint32_t)__cvta_generic_to_shared(sW) +
                     (lrow * SW + wh * 64 + lcol * 8) * 2;

    // initial prefetch -> buffer 0
    {
        int chunk = blockIdx.x;
        for (int t = tid; t < LINES; t += 512) {
            int r = t / PER_ROW;
            int col = t - r * PER_ROW;
            int row = chunk * 128 + r;
            int ok = row < N_NODES;
            const __half* src = in + (size_t)(ok ? row : 0) * IN + col * 8;
            cp16(sA0u + (r * SA + col * 8) * 2, src, ok ? 16 : 0);
        }
        CP_COMMIT();
    }

    int j = 0;
    for (int c = blockIdx.x; c < NCHUNK; c += GEMM_GRID, ++j) {
        int cn = c + GEMM_GRID;
        if (cn < NCHUNK) {
            uint32_t sAu = (j & 1) ? sA0u : sA1u;
            for (int t = tid; t < LINES; t += 512) {
                int r = t / PER_ROW;
                int col = t - r * PER_ROW;
                int row = cn * 128 + r;
                int ok = row < N_NODES;
                const __half* src = in + (size_t)(ok ? row : 0) * IN + col * 8;
                cp16(sAu + (r * SA + col * 8) * 2, src, ok ? 16 : 0);
            }
            CP_COMMIT();
            CP_WAIT(1);
        } else {
            CP_WAIT(0);
        }
        __syncthreads();

        uint32_t aBase = ((j & 1) ? sA1u : sA0u) + aOff;
        float acc[8][4] = {};
#pragma unroll
        for (int ks = 0; ks < IN / 16; ++ks) {
            uint32_t a0, a1, a2, a3;
            ldsm_x4(a0, a1, a2, a3, aBase + ks * 32);
#pragma unroll
            for (int jj = 0; jj < 4; ++jj) {
                uint32_t b0, b1, b2, b3;
                ldsm_x4_t(b0, b1, b2, b3, wBase + ks * 16 * SW * 2 + jj * 32);
                mma16816(acc[2 * jj], a0, a1, a2, a3, b0, b1);
                mma16816(acc[2 * jj + 1], a0, a1, a2, a3, b2, b3);
            }
        }

        int r_lo = c * 128 + mg * 16 + (lane >> 2);
        int cbase = wh * 64 + (lane & 3) * 2;
        float dv_lo = (r_lo < N_NODES) ? g_dinv[r_lo] : 0.f;
        float dv_hi = (r_lo + 8 < N_NODES) ? g_dinv[r_lo + 8] : 0.f;
#pragma unroll
        for (int jj = 0; jj < 8; ++jj) {
            int col = cbase + jj * 8;
            if (r_lo < N_NODES) {
                __half2 h = __floats2half2_rn(acc[jj][0] * dv_lo, acc[jj][1] * dv_lo);
                *reinterpret_cast<__half2*>(&g_mh[(size_t)r_lo * HIDDEN + col]) = h;
            }
            if (r_lo + 8 < N_NODES) {
                __half2 h = __floats2half2_rn(acc[jj][2] * dv_hi, acc[jj][3] * dv_hi);
                *reinterpret_cast<__half2*>(&g_mh[(size_t)(r_lo + 8) * HIDDEN + col]) = h;
            }
        }
        __syncthreads();
    }
}

// ---------------- fused GEMM1 + CSR build (fat kernel: stream-free overlap) ----
// Blocks [0, GEMM_GRID): pipelined GEMM1.  Blocks [GEMM_GRID, +CSR_BLOCKS):
// counting-sort scatter (independent work; overlaps GEMM on-chip).
__global__ void __launch_bounds__(512) k_gemm1_csr(const float* __restrict__ W,
                                                   const void* ei) {
    if (blockIdx.x < GEMM_GRID) {
        gemm_body<EMBED, true>(W);
    } else {
        int is64 = g_is64;
        int e = (blockIdx.x - GEMM_GRID) * 512 + threadIdx.x;
        if (e < N_EDGES) {
            int s = (int)load_idx(ei, e, is64);
            int d = (int)load_idx(ei, N_EDGES + e, is64);
            int pos = atomicAdd(&g_cursor[d], 1);
            g_csr32[pos] = s;
        }
    }
}

// ---------------- standalone GEMM (layers 2,3) ----------------
template <int IN, bool FROM_H0>
__global__ void __launch_bounds__(512) k_gemm(const float* __restrict__ W) {
    gemm_body<IN, FROM_H0>(W);
}

// ---------------- edge aggregate (CSR): 16 lanes per dst node ----------------
// g_xh[n] = relu( dinv[n] * ( sum_src m'[src] + m'[n] ) + b ),  m' = dinv*m.
// Depth-3 rolling prefetch: 2 gathers in flight per chain (was 1).
__global__ void __launch_bounds__(256) k_edge(const float* __restrict__ b) {
    int t = blockIdx.x * 256 + threadIdx.x;
    int node = t >> 4;
    int lane = threadIdx.x & 15;          // 8 cols per lane
    if (node >= N_NODES) return;
    int r0 = g_rowptr[node];
    int r1 = g_rowptr[node + 1];
    const uint4* mh4 = reinterpret_cast<const uint4*>(g_mh);   // 8 halves per uint4
    const unsigned long long ONE = pack2(1.0f, 1.0f);

    unsigned long long acc0 = 0, acc1 = 0, acc2 = 0, acc3 = 0;
    uint4 rA = make_uint4(0, 0, 0, 0), rB = make_uint4(0, 0, 0, 0);
    if (r0 < r1) {
        int s = g_csr32[r0];
        rA = mh4[(size_t)s * (HIDDEN / 8) + lane];
    }
    if (r0 + 1 < r1) {
        int s = g_csr32[r0 + 1];
        rB = mh4[(size_t)s * (HIDDEN / 8) + lane];
    }
    for (int j = r0; j < r1; ++j) {
        uint4 rC = rB;
        if (j + 2 < r1) {
            int s = g_csr32[j + 2];
            rC = mh4[(size_t)s * (HIDDEN / 8) + lane];
        }
        float2 f0 = __half22float2(*reinterpret_cast<__half2*>(&rA.x));
        float2 f1 = __half22float2(*reinterpret_cast<__half2*>(&rA.y));
        float2 f2 = __half22float2(*reinterpret_cast<__half2*>(&rA.z));
        float2 f3 = __half22float2(*reinterpret_cast<__half2*>(&rA.w));
        fma2(acc0, ONE, pack2(f0.x, f0.y));
        fma2(acc1, ONE, pack2(f1.x, f1.y));
        fma2(acc2, ONE, pack2(f2.x, f2.y));
        fma2(acc3, ONE, pack2(f3.x, f3.y));
        rA = rB;
        rB = rC;
    }
    // self term, post-scale by dinv[n], bias, relu
    uint4 ms = mh4[(size_t)node * (HIDDEN / 8) + lane];
    float dv = g_dinv[node];
    float4 bb0 = *reinterpret_cast<const float4*>(&b[lane * 8]);
    float4 bb1 = *reinterpret_cast<const float4*>(&b[lane * 8 + 4]);
    float2 m0 = __half22float2(*reinterpret_cast<__half2*>(&ms.x));
    float2 m1 = __half22float2(*reinterpret_cast<__half2*>(&ms.y));
    float2 m2 = __half22float2(*reinterpret_cast<__half2*>(&ms.z));
    float2 m3 = __half22float2(*reinterpret_cast<__half2*>(&ms.w));
    float2 a0 = unpack2(acc0), a1 = unpack2(acc1);
    float2 a2 = unpack2(acc2), a3 = unpack2(acc3);
    float o0 = fmaxf(fmaf(a0.x + m0.x, dv, bb0.x), 0.f);
    float o1 = fmaxf(fmaf(a0.y + m0.y, dv, bb0.y), 0.f);
    float o2 = fmaxf(fmaf(a1.x + m1.x, dv, bb0.z), 0.f);
    float o3 = fmaxf(fmaf(a1.y + m1.y, dv, bb0.w), 0.f);
    float o4 = fmaxf(fmaf(a2.x + m2.x, dv, bb1.x), 0.f);
    float o5 = fmaxf(fmaf(a2.y + m2.y, dv, bb1.y), 0.f);
    float o6 = fmaxf(fmaf(a3.x + m3.x, dv, bb1.z), 0.f);
    float o7 = fmaxf(fmaf(a3.y + m3.y, dv, bb1.w), 0.f);
    __half2 h0 = __floats2half2_rn(o0, o1);
    __half2 h1 = __floats2half2_rn(o2, o3);
    __half2 h2 = __floats2half2_rn(o4, o5);
    __half2 h3 = __floats2half2_rn(o6, o7);
    uint4 u = make_uint4(*reinterpret_cast<uint32_t*>(&h0),
                         *reinterpret_cast<uint32_t*>(&h1),
                         *reinterpret_cast<uint32_t*>(&h2),
                         *reinterpret_cast<uint32_t*>(&h3));
    reinterpret_cast<uint4*>(g_xh)[(size_t)node * (HIDDEN / 8) + lane] = u;
}

// ---------------- pooling (batch sorted -> register accumulation) ----------------
#define POOL_CHUNK 512
__global__ void __launch_bounds__(128) k_pool(const void* batch) {
    int is64 = g_is64;
    int t = threadIdx.x;
    int n0 = blockIdx.x * POOL_CHUNK;
    int n1 = n0 + POOL_CHUNK;
    if (n1 > N_NODES) n1 = N_NODES;
    float acc = 0.0f, cnt = 0.0f;
    int cur = -1;
    for (int n = n0; n < n1; ++n) {
        int gidx = (int)load_idx(batch, n, is64);
        if (gidx != cur) {
            if (cur >= 0) {
                atomicAdd(&g_pool[cur * HIDDEN + t], acc);
                if (t == 0) atomicAdd(&g_cnt[cur], cnt);
            }
            cur = gidx;
            acc = 0.0f;
            cnt = 0.0f;
        }
        acc += __half2float(g_xh[(size_t)n * HIDDEN + t]);   // already relu'd
        cnt += 1.0f;
    }
    if (cur >= 0) {
        atomicAdd(&g_pool[cur * HIDDEN + t], acc);
        if (t == 0) atomicAdd(&g_cnt[cur], cnt);
    }
}

// ---------------- final: out = (pool / cnt) @ Wp + bp ----------------
__global__ void k_final(const float* __restrict__ Wp, const float* __restrict__ bp,
                        float* __restrict__ out) {
    int t = blockIdx.x * blockDim.x + threadIdx.x;
    if (t >= N_GRAPHS * HIDDEN) return;
    int g = t >> 7;
    int j = t & 127;
    float inv = 1.0f / fmaxf(g_cnt[g], 1.0f);
    float acc = bp[j];
#pragma unroll 8
    for (int k = 0; k < HIDDEN; ++k)
        acc = fmaf(g_pool[g * HIDDEN + k] * inv, Wp[k * HIDDEN + j], acc);
    out[t] = acc;
}

// ---------------- launch ----------------
extern "C" void kernel_launch(void* const* d_in, const int* in_sizes, int n_in,
                              void* d_out, int out_size) {
    const void* x     = d_in[0];
    const void* ei    = d_in[1];
    const void* batch = d_in[2];
    const float* emb  = (const float*)d_in[3];
    const float* W1   = (const float*)d_in[4];
    const float* b1   = (const float*)d_in[5];
    const float* W2   = (const float*)d_in[6];
    const float* b2   = (const float*)d_in[7];
    const float* W3   = (const float*)d_in[8];
    const float* b3   = (const float*)d_in[9];
    const float* Wp   = (const float*)d_in[10];
    const float* bp   = (const float*)d_in[11];
    float* out = (float*)d_out;

    // smem: W + 2x A chunk buffers
    constexpr int SMEM1 = (EMBED * (HIDDEN + 8) + 2 * 128 * (EMBED + 8)) * 2;   // 53 KB
    constexpr int SMEM2 = (HIDDEN * (HIDDEN + 8) + 2 * 128 * (HIDDEN + 8)) * 2; // 102 KB
    cudaFuncSetAttribute(k_gemm1_csr,
                         cudaFuncAttributeMaxDynamicSharedMemorySize, SMEM1);
    cudaFuncSetAttribute(k_gemm<HIDDEN, false>,
                         cudaFuncAttributeMaxDynamicSharedMemorySize, SMEM2);

    const int EDGE_GRID = (N_NODES * 16 + 255) / 256;     // 6250

    k_init<<<(N_NODES + 255) / 256, 256>>>(ei);                              // 0
    k_count_embed<<<(N_EDGES + 255) / 256, 256>>>(ei, x, emb);               // 1
    k_scan1<<<(N_NODES + 255) / 256, 256>>>();                               // 2
    k_scan2<<<1, 512>>>();                                                   // 3
    k_scan3<<<(N_NODES + 255) / 256, 256>>>();                               // 4
    k_gemm1_csr<<<GEMM_GRID + CSR_BLOCKS, 512, SMEM1>>>(W1, ei);             // 5
    k_edge<<<EDGE_GRID, 256>>>(b1);                                          // 6
    k_gemm<HIDDEN, false><<<GEMM_GRID, 512, SMEM2>>>(W2);                    // 7
    k_edge<<<EDGE_GRID, 256>>>(b2);                                          // 8
    k_gemm<HIDDEN, false><<<GEMM_GRID, 512, SMEM2>>>(W3);                    // 9
    k_edge<<<EDGE_GRID, 256>>>(b3);                                          // 10
    k_pool<<<(N_NODES + POOL_CHUNK - 1) / POOL_CHUNK, 128>>>(batch);         // 11
    k_final<<<(N_GRAPHS * HIDDEN + 255) / 256, 256>>>(Wp, bp, out);          // 12
}